// round 1
// baseline (speedup 1.0000x reference)
#include <cuda_runtime.h>

#define N_NODES 100000
#define E_EDGES 1600000
#define D 64
#define PITCH 68   // smem row pitch in floats (16B aligned, bank-skewed)

// Scratch (device globals — no dynamic allocation allowed)
__device__ float g_acc[2 * N_NODES * D];   // [v-sums | u-sums]
__device__ float g_deg[2 * N_NODES];       // [deg_v | deg_u]
__device__ float g_hweb[N_NODES * D];      // h @ We_h^T + be  (per-node, gathered per-edge)

// ---------------------------------------------------------------------------
// Stage 1: scatter-add efeats into per-node sums (both directions) + degrees
// One thread per (edge, float4-chunk): E*16 threads.
// ---------------------------------------------------------------------------
__device__ __forceinline__ void red_add_v4(float* p, float4 f) {
    asm volatile("red.global.add.v4.f32 [%0], {%1,%2,%3,%4};"
                 :: "l"(p), "f"(f.x), "f"(f.y), "f"(f.z), "f"(f.w) : "memory");
}

__global__ void scatter_kernel(const float4* __restrict__ ef4,
                               const int* __restrict__ u,
                               const int* __restrict__ v) {
    int idx = blockIdx.x * blockDim.x + threadIdx.x;  // exactly E*16
    int e = idx >> 4;
    int c = idx & 15;
    float4 f = ef4[idx];          // coalesced: idx == e*16 + c
    int vv = v[e];
    int uu = u[e];
    red_add_v4(&g_acc[(vv << 6) + (c << 2)], f);
    red_add_v4(&g_acc[(N_NODES << 6) + (uu << 6) + (c << 2)], f);
    if (c == 0) {
        atomicAdd(&g_deg[vv], 1.0f);
        atomicAdd(&g_deg[N_NODES + uu], 1.0f);
    }
}

// ---------------------------------------------------------------------------
// Stage 2: per-node — means, h = relu(cat @ Wn^T + bn), hweb = h @ We_h^T + be
// Block = 256 threads, 64 nodes/block. Two register-blocked GEMMs (4x4/thread).
// ---------------------------------------------------------------------------
__global__ void node_kernel(const float* __restrict__ Wn,
                            const float* __restrict__ bn,
                            const float* __restrict__ We,
                            const float* __restrict__ be,
                            float* __restrict__ h_out) {
    extern __shared__ float smem[];
    float* A_s = smem;                 // [128][PITCH]  cat transposed (then C_s)
    float* B_s = smem + 128 * PITCH;   // [128][PITCH]  Wn transposed  (then H_s)

    int t = threadIdx.x;
    int nb = blockIdx.x * 64;

    // ---- stage A: means, transposed A_s[k][node_local]
    {
        int nl = t >> 2, q = t & 3;
        int n = nb + nl;
        bool ok = (n < N_NODES);
        float rv = 0.f, ru = 0.f;
        if (ok) {
            rv = 1.0f / fmaxf(g_deg[n], 1.0f);
            ru = 1.0f / fmaxf(g_deg[N_NODES + n], 1.0f);
        }
#pragma unroll
        for (int i = 0; i < 8; i++) {
            int k4 = q + 4 * i;                 // 0..31  (k = k4*4)
            float4 f = make_float4(0.f, 0.f, 0.f, 0.f);
            float s = 0.f;
            if (ok) {
                if (k4 < 16) { f = ((const float4*)g_acc)[n * 16 + k4]; s = rv; }
                else         { f = ((const float4*)g_acc)[(N_NODES + n) * 16 + (k4 - 16)]; s = ru; }
            }
            int k = k4 << 2;
            A_s[(k + 0) * PITCH + nl] = f.x * s;
            A_s[(k + 1) * PITCH + nl] = f.y * s;
            A_s[(k + 2) * PITCH + nl] = f.z * s;
            A_s[(k + 3) * PITCH + nl] = f.w * s;
        }
    }
    // ---- stage B: Wn [64][128] transposed -> B_s[k][o]
    {
        int o = t >> 2, q = t & 3;
#pragma unroll
        for (int i = 0; i < 8; i++) {
            int k4 = q + 4 * i;
            float4 f = ((const float4*)Wn)[o * 32 + k4];
            int k = k4 << 2;
            B_s[(k + 0) * PITCH + o] = f.x;
            B_s[(k + 1) * PITCH + o] = f.y;
            B_s[(k + 2) * PITCH + o] = f.z;
            B_s[(k + 3) * PITCH + o] = f.w;
        }
    }
    __syncthreads();

    int tx = t & 15, ty = t >> 4;
    float acc[4][4] = {};
#pragma unroll 8
    for (int k = 0; k < 128; k++) {
        float4 a = *reinterpret_cast<const float4*>(&A_s[k * PITCH + (tx << 2)]);
        float4 b = *reinterpret_cast<const float4*>(&B_s[k * PITCH + (ty << 2)]);
        float av[4] = {a.x, a.y, a.z, a.w};
        float bv[4] = {b.x, b.y, b.z, b.w};
#pragma unroll
        for (int i = 0; i < 4; i++)
#pragma unroll
            for (int j = 0; j < 4; j++)
                acc[i][j] = fmaf(av[i], bv[j], acc[i][j]);
    }

    float4 bnv = ((const float4*)bn)[ty];
    float bnb[4] = {bnv.x, bnv.y, bnv.z, bnv.w};
    float hv[4][4];
#pragma unroll
    for (int i = 0; i < 4; i++)
#pragma unroll
        for (int j = 0; j < 4; j++)
            hv[i][j] = fmaxf(acc[i][j] + bnb[j], 0.0f);

    __syncthreads();  // all GEMM1 smem reads done; A_s/B_s regions now reusable

    float* C_s = A_s;  // [64][PITCH]  We_h transposed
    float* H_s = B_s;  // [64][PITCH]  h transposed

    // write h: gmem + transposed smem
#pragma unroll
    for (int i = 0; i < 4; i++) {
        int n = nb + (tx << 2) + i;
#pragma unroll
        for (int j = 0; j < 4; j++)
            H_s[((ty << 2) + j) * PITCH + (tx << 2) + i] = hv[i][j];
        if (n < N_NODES)
            *reinterpret_cast<float4*>(&h_out[n * 64 + (ty << 2)]) =
                make_float4(hv[i][0], hv[i][1], hv[i][2], hv[i][3]);
    }
    // stage C: We_h = We[:, :64] transposed -> C_s[k][o2]
    {
        int o2 = t >> 2, q = t & 3;
#pragma unroll
        for (int i = 0; i < 4; i++) {
            int k4 = q + 4 * i;  // 0..15
            float4 f = ((const float4*)We)[o2 * 32 + k4];
            int k = k4 << 2;
            C_s[(k + 0) * PITCH + o2] = f.x;
            C_s[(k + 1) * PITCH + o2] = f.y;
            C_s[(k + 2) * PITCH + o2] = f.z;
            C_s[(k + 3) * PITCH + o2] = f.w;
        }
    }
    __syncthreads();

    float acc2[4][4] = {};
#pragma unroll 8
    for (int k = 0; k < 64; k++) {
        float4 a = *reinterpret_cast<const float4*>(&H_s[k * PITCH + (tx << 2)]);
        float4 b = *reinterpret_cast<const float4*>(&C_s[k * PITCH + (ty << 2)]);
        float av[4] = {a.x, a.y, a.z, a.w};
        float bv[4] = {b.x, b.y, b.z, b.w};
#pragma unroll
        for (int i = 0; i < 4; i++)
#pragma unroll
            for (int j = 0; j < 4; j++)
                acc2[i][j] = fmaf(av[i], bv[j], acc2[i][j]);
    }

    float4 bev = ((const float4*)be)[ty];
    float beb[4] = {bev.x, bev.y, bev.z, bev.w};
#pragma unroll
    for (int i = 0; i < 4; i++) {
        int n = nb + (tx << 2) + i;
        if (n < N_NODES)
            *reinterpret_cast<float4*>(&g_hweb[n * 64 + (ty << 2)]) =
                make_float4(acc2[i][0] + beb[0], acc2[i][1] + beb[1],
                            acc2[i][2] + beb[2], acc2[i][3] + beb[3]);
    }
}

// ---------------------------------------------------------------------------
// Stage 3: per-edge — edge = hweb[u[e]] + efeats[e] @ We_e^T
// Block = 256 threads, 64 edges x 64 outs tile, 4x4 micro-tile.
// ---------------------------------------------------------------------------
__global__ void edge_kernel(const float* __restrict__ efeats,
                            const int* __restrict__ u,
                            const float* __restrict__ We,
                            float* __restrict__ edge_out) {
    extern __shared__ float smem[];
    float* A_s = smem;               // [64][PITCH]  efeats tile transposed
    float* B_s = smem + 64 * PITCH;  // [64][PITCH]  We_e transposed
    __shared__ int u_s[64];

    int t = threadIdx.x;
    int eb = blockIdx.x * 64;

    if (t < 64) u_s[t] = u[eb + t];

    // stage A: efeats[eb..eb+63][0..63] -> A_s[k][e]
    {
        int el = t >> 2, q = t & 3;
        const float4* erow = (const float4*)efeats + (size_t)(eb + el) * 16;
#pragma unroll
        for (int i = 0; i < 4; i++) {
            int k4 = q + 4 * i;  // 0..15
            float4 f = erow[k4];
            int k = k4 << 2;
            A_s[(k + 0) * PITCH + el] = f.x;
            A_s[(k + 1) * PITCH + el] = f.y;
            A_s[(k + 2) * PITCH + el] = f.z;
            A_s[(k + 3) * PITCH + el] = f.w;
        }
    }
    // stage B: We_e = We[:, 64:128] transposed -> B_s[k][o]
    {
        int o = t >> 2, q = t & 3;
#pragma unroll
        for (int i = 0; i < 4; i++) {
            int k4 = 16 + q + 4 * i;  // float4s 16..31 of row (cols 64..127)
            float4 f = ((const float4*)We)[o * 32 + k4];
            int k = (k4 - 16) << 2;
            B_s[(k + 0) * PITCH + o] = f.x;
            B_s[(k + 1) * PITCH + o] = f.y;
            B_s[(k + 2) * PITCH + o] = f.z;
            B_s[(k + 3) * PITCH + o] = f.w;
        }
    }
    __syncthreads();

    int tx = t & 15, ty = t >> 4;
    float acc[4][4] = {};
#pragma unroll 16
    for (int k = 0; k < 64; k++) {
        float4 a = *reinterpret_cast<const float4*>(&A_s[k * PITCH + (tx << 2)]);
        float4 b = *reinterpret_cast<const float4*>(&B_s[k * PITCH + (ty << 2)]);
        float av[4] = {a.x, a.y, a.z, a.w};
        float bv[4] = {b.x, b.y, b.z, b.w};
#pragma unroll
        for (int i = 0; i < 4; i++)
#pragma unroll
            for (int j = 0; j < 4; j++)
                acc[i][j] = fmaf(av[i], bv[j], acc[i][j]);
    }

#pragma unroll
    for (int i = 0; i < 4; i++) {
        int e = eb + (tx << 2) + i;
        int uu = u_s[(tx << 2) + i];
        float4 g = *reinterpret_cast<const float4*>(&g_hweb[uu * 64 + (ty << 2)]);
        *reinterpret_cast<float4*>(&edge_out[(size_t)e * 64 + (ty << 2)]) =
            make_float4(acc[i][0] + g.x, acc[i][1] + g.y,
                        acc[i][2] + g.z, acc[i][3] + g.w);
    }
}

// ---------------------------------------------------------------------------
extern "C" void kernel_launch(void* const* d_in, const int* in_sizes, int n_in,
                              void* d_out, int out_size) {
    // inputs: [0]=nfeats (unused), [1]=efeats, [2]=u, [3]=v, [4]=Wn, [5]=bn, [6]=We, [7]=be
    const float* efeats = (const float*)d_in[1];
    const int*   u      = (const int*)d_in[2];
    const int*   v      = (const int*)d_in[3];
    const float* Wn     = (const float*)d_in[4];
    const float* bn     = (const float*)d_in[5];
    const float* We     = (const float*)d_in[6];
    const float* be     = (const float*)d_in[7];

    float* out      = (float*)d_out;
    float* h_out    = out;                               // [N,64]
    float* edge_out = out + (size_t)N_NODES * 64;        // [E,64]

    void* accp = nullptr; cudaGetSymbolAddress(&accp, g_acc);
    void* degp = nullptr; cudaGetSymbolAddress(&degp, g_deg);
    cudaMemsetAsync(accp, 0, sizeof(float) * 2 * N_NODES * D, 0);
    cudaMemsetAsync(degp, 0, sizeof(float) * 2 * N_NODES, 0);

    scatter_kernel<<<(E_EDGES * 16) / 256, 256>>>((const float4*)efeats, u, v);

    int node_smem = 2 * 128 * PITCH * (int)sizeof(float);  // 69632 B
    cudaFuncSetAttribute(node_kernel, cudaFuncAttributeMaxDynamicSharedMemorySize, node_smem);
    node_kernel<<<(N_NODES + 63) / 64, 256, node_smem>>>(Wn, bn, We, be, h_out);

    int edge_smem = 2 * 64 * PITCH * (int)sizeof(float);   // 34816 B
    edge_kernel<<<E_EDGES / 64, 256, edge_smem>>>(efeats, u, We, edge_out);
}